// round 8
// baseline (speedup 1.0000x reference)
#include <cuda_runtime.h>
#include <cstdint>

// resRNN: x(256,1024,8), W1(521,512), b1(512), W2(512,1), b2(1)
// out = [output(256,1024,1) | implied_storage(256,1024,1)]
//
// 128 CTAs = 16 rowgroups x 8 colgroups. Cluster(8) = one rowgroup.
// Each CTA: 16 batch rows x 64 hidden cols, W1 slice resident in smem.
// 8 warps with unbalanced k-split [48,68,68,68,88,68,68,68] (SMSP pairs sum 136).
// Warp-local transpose (no block sync before mainloop); out/s gather folded into
// warp 0; s contribution added in the reduce phase.

#define TPB 256

static __device__ float g_hx[2][256][512];       // double-buffered hidden state
static __device__ float g_part[2][16][8][16];    // per-(rg,cg,row) readout partials

// shared memory layout (float offsets); inpT stride = 20 (16 rows + 4 pad)
#define OFF_W    0              // 544*64   = 34816 floats
#define OFF_IT   34816          // 544*20   = 10880 floats (inpT[k][20])
#define OFF_RED  45696          // 8*16*68  =  8704 floats
#define OFF_B1   54400          // 64
#define OFF_W2   54464          // 64
#define OFF_S    54528          // 16
#define SMEM_FLOATS 54544
#define SMEM_BYTES (SMEM_FLOATS * 4)

__device__ __forceinline__ float tanh_ex(float v) {
    // exact-enough tanh: 1 - 2/(e^{2v}+1); saturates correctly for |v| large.
    float e = __expf(2.0f * v);
    return 1.0f - __fdividef(2.0f, e + 1.0f);
}

__global__ void __cluster_dims__(8, 1, 1) __launch_bounds__(256, 1)
resRNN_kernel(const float* __restrict__ x, const float* __restrict__ W1,
              const float* __restrict__ b1, const float* __restrict__ W2,
              const float* __restrict__ b2, float* __restrict__ dout)
{
    extern __shared__ float sm[];
    float* Wsm  = sm + OFF_W;
    float* inpT = sm + OFF_IT;
    float* red  = sm + OFF_RED;
    float* b1s  = sm + OFF_B1;
    float* w2s  = sm + OFF_W2;
    float* s_sm = sm + OFF_S;

    const int tid  = threadIdx.x;
    const int warp = tid >> 5;
    const int lane = tid & 31;
    const int cg   = blockIdx.x;   // colgroup 0..7
    const int rg   = blockIdx.y;   // rowgroup 0..15
    const int row0 = rg * 16;

    // per-warp k ranges; SMSP pairs (w, w+4) each sum to 136 k
    const int KSTART[8] = {0, 48, 116, 184, 252, 340, 408, 476};
    const int KCNT[8]   = {48, 68, 68, 68, 88, 68, 68, 68};
    const int k0 = KSTART[warp];
    const int kc = KCNT[warp];
    // hx columns this warp transposes: k-rows [k0, k0+kc) minus x/s rows 0..8
    const int c0 = (k0 > 9 ? k0 - 9 : 0);
    const int c1 = (k0 + kc - 9 < 512 ? k0 + kc - 9 : 512);

    // ---- init: load W1 slice [544 x 64] (zero-pad k>=521), zero inpT ----
    for (int i = tid; i < 544 * 16; i += TPB) {
        int k = i >> 4, f4 = i & 15;
        float4 v = make_float4(0.f, 0.f, 0.f, 0.f);
        if (k < 521) v = *(const float4*)&W1[k * 512 + cg * 64 + f4 * 4];
        *(float4*)&Wsm[k * 64 + f4 * 4] = v;
    }
    for (int i = tid; i < 544 * 20; i += TPB) inpT[i] = 0.f;
    if (tid < 64) { b1s[tid] = b1[cg * 64 + tid]; w2s[tid] = W2[cg * 64 + tid]; }
    const float b2v = b2[0];
    float* outp = dout;
    float* stop = dout + 256 * 1024;

    // pre-loop: stage x_0; s_0 = x_0[0]; prefetch x_1
    if (tid < 128) {
        int r = tid >> 3, c = tid & 7;
        inpT[c * 20 + r] = x[(row0 + r) * 8192 + c];
    }
    if (tid < 16) {
        float s = x[(row0 + tid) * 8192];      // s_0 (prev out = 0)
        s_sm[tid] = s;
        if (cg == 0) stop[(row0 + tid) * 1024] = s;
    }
    // warp 0 owns x staging: lane -> (row = lane>>1, comps = (lane&1)*4 .. +3)
    const int xrow = lane >> 1, xc4 = (lane & 1) * 4;
    float4 xpre4 = make_float4(0.f, 0.f, 0.f, 0.f);
    float x0pre = 0.f;
    if (warp == 0) {
        xpre4 = *(const float4*)&x[(row0 + xrow) * 8192 + 8 + xc4];   // x_1
        if (lane < 16) x0pre = x[(row0 + lane) * 8192 + 8];           // x_1[0]
    }
    __syncthreads();

    for (int t = 0; t < 1024; ++t) {
        const int pw = t & 1;        // write parity
        const int pr = pw ^ 1;       // read parity

        // ---- Phase A (per-warp, no block sync) ----
        if (t > 0) {
            if (warp == 0 && lane < 16) {
                // gather out_{t-1}, mass balance (overlaps all warps' work)
                float o = b2v;
                #pragma unroll
                for (int g = 0; g < 8; ++g) o += __ldcg(&g_part[pr][rg][g][lane]);
                float s = s_sm[lane] + x0pre - o;
                s_sm[lane] = s;
                if (cg == 0) {
                    outp[(row0 + lane) * 1024 + (t - 1)] = o;
                    stop[(row0 + lane) * 1024 + t] = s;
                }
            }
            // warp-local transpose of this warp's hx columns
            for (int c = c0 + lane; c < c1; c += 32) {
                float v[16];
                #pragma unroll
                for (int r = 0; r < 16; ++r) v[r] = __ldcg(&g_hx[pr][row0 + r][c]);
                float* d = &inpT[(9 + c) * 20];
                #pragma unroll
                for (int q = 0; q < 4; ++q)
                    *(float4*)(d + 4 * q) =
                        make_float4(v[4*q], v[4*q+1], v[4*q+2], v[4*q+3]);
            }
        }
        __syncwarp();

        // ---- mainloop: warp covers k in [k0, k0+kc), 16 rows x cols (2*lane, 2*lane+1)
        unsigned long long acc0[8], acc1[8];
        #pragma unroll
        for (int i = 0; i < 8; ++i) { acc0[i] = 0ull; acc1[i] = 0ull; }
        {
            const float* Ip = inpT + k0 * 20;
            const float* Wp = Wsm + k0 * 64 + 2 * lane;
            #pragma unroll 4
            for (int kk = 0; kk < kc; ++kk) {
                unsigned long long pr_[8];
                #pragma unroll
                for (int j = 0; j < 4; ++j) {
                    ulonglong2 q = *(const ulonglong2*)(Ip + kk * 20 + 4 * j);
                    pr_[2 * j] = q.x; pr_[2 * j + 1] = q.y;
                }
                float2 wv = *(const float2*)(Wp + kk * 64);
                unsigned long long w00, w11;
                asm("mov.b64 %0, {%1, %1};" : "=l"(w00) : "f"(wv.x));
                asm("mov.b64 %0, {%1, %1};" : "=l"(w11) : "f"(wv.y));
                #pragma unroll
                for (int p = 0; p < 8; ++p) {
                    asm("fma.rn.f32x2 %0, %1, %2, %0;" : "+l"(acc0[p]) : "l"(pr_[p]), "l"(w00));
                    asm("fma.rn.f32x2 %0, %1, %2, %0;" : "+l"(acc1[p]) : "l"(pr_[p]), "l"(w11));
                }
            }
        }

        // ---- spill k-partials, reduce (+ s term), tanh, emit hx + readout partial
        #pragma unroll
        for (int p = 0; p < 8; ++p) {
            float2 a0 = *(float2*)&acc0[p];   // (row 2p, 2p+1) col even
            float2 a1 = *(float2*)&acc1[p];   // col odd
            *(float2*)&red[(warp * 16 + 2 * p)     * 68 + 2 * lane] = make_float2(a0.x, a1.x);
            *(float2*)&red[(warp * 16 + 2 * p + 1) * 68 + 2 * lane] = make_float2(a0.y, a1.y);
        }
        __syncthreads();
        {
            int r = tid >> 4, c4 = (tid & 15) * 4;
            float4 v = make_float4(0.f, 0.f, 0.f, 0.f);
            #pragma unroll
            for (int w = 0; w < 8; ++w) {
                float4 p = *(const float4*)&red[(w * 16 + r) * 68 + c4];
                v.x += p.x; v.y += p.y; v.z += p.z; v.w += p.w;
            }
            // fold in s * W1[row 8] (inpT[8] is permanently zero)
            float s = s_sm[r];
            float4 w8 = *(const float4*)&Wsm[8 * 64 + c4];
            v.x += s * w8.x; v.y += s * w8.y; v.z += s * w8.z; v.w += s * w8.w;

            v.x = tanh_ex(v.x + b1s[c4 + 0]);
            v.y = tanh_ex(v.y + b1s[c4 + 1]);
            v.z = tanh_ex(v.z + b1s[c4 + 2]);
            v.w = tanh_ex(v.w + b1s[c4 + 3]);
            *(float4*)&g_hx[pw][row0 + r][cg * 64 + c4] = v;
            float p = v.x * w2s[c4] + v.y * w2s[c4 + 1] + v.z * w2s[c4 + 2] + v.w * w2s[c4 + 3];
            #pragma unroll
            for (int off = 8; off > 0; off >>= 1)
                p += __shfl_xor_sync(0xffffffffu, p, off);
            if ((tid & 15) == 0) g_part[pw][rg][cg][r] = p;
        }

        // ---- split cluster barrier; warp 0 stages x_{t+1} in the gap ----
        asm volatile("barrier.cluster.arrive.aligned;" ::: "memory");
        if (t < 1023 && warp == 0) {
            inpT[(xc4 + 0) * 20 + xrow] = xpre4.x;
            inpT[(xc4 + 1) * 20 + xrow] = xpre4.y;
            inpT[(xc4 + 2) * 20 + xrow] = xpre4.z;
            inpT[(xc4 + 3) * 20 + xrow] = xpre4.w;
            if (t < 1022)
                xpre4 = *(const float4*)&x[(row0 + xrow) * 8192 + (t + 2) * 8 + xc4];
            if (lane < 16) x0pre = x[(row0 + lane) * 8192 + (t + 1) * 8];
        }
        asm volatile("barrier.cluster.wait.aligned;" ::: "memory");
    }

    // epilogue: final output value out_{L-1}
    if (cg == 0 && tid < 16) {
        float o = b2v;
        #pragma unroll
        for (int g = 0; g < 8; ++g) o += __ldcg(&g_part[1][rg][g][tid]);
        outp[(row0 + tid) * 1024 + 1023] = o;
    }
}

extern "C" void kernel_launch(void* const* d_in, const int* in_sizes, int n_in,
                              void* d_out, int out_size) {
    const float* x  = (const float*)d_in[0];
    const float* W1 = (const float*)d_in[1];
    const float* b1 = (const float*)d_in[2];
    const float* W2 = (const float*)d_in[3];
    const float* b2 = (const float*)d_in[4];
    float* out = (float*)d_out;

    cudaFuncSetAttribute(resRNN_kernel, cudaFuncAttributeMaxDynamicSharedMemorySize, SMEM_BYTES);

    dim3 grid(8, 16, 1);   // cluster_dims (8,1,1): one cluster per rowgroup
    dim3 block(TPB, 1, 1);
    resRNN_kernel<<<grid, block, SMEM_BYTES>>>(x, W1, b1, W2, b2, out);
}